// round 2
// baseline (speedup 1.0000x reference)
#include <cuda_runtime.h>

#define EPS 1e-8f

namespace {
constexpr int B = 256;
constexpr int S = 24;
constexpr int D = 256;
constexpr int N = 8192;
}

// ---------------------------------------------------------------------------
// Kernel A: new_slots [B,S,D] and slot_nums [B]
// grid = B blocks, 256 threads (one per d)
// ---------------------------------------------------------------------------
__global__ void __launch_bounds__(256) slots_kernel(
    const float* __restrict__ slots,     // [B,S,D]
    const int* __restrict__ clusters,    // [B,S] (int32 — JAX default, no x64)
    float* __restrict__ out_slots,       // [B,S,D]
    float* __restrict__ out_nums)        // [B]
{
    int b = blockIdx.x;
    int d = threadIdx.x;

    __shared__ int cl[S];
    __shared__ int cnt[S];

    if (d < S) cl[d] = clusters[b * S + d];
    __syncthreads();
    if (d < S) {
        int c = 0;
        #pragma unroll
        for (int j = 0; j < S; j++) c += (cl[j] == d);
        cnt[d] = c;
    }
    __syncthreads();

    // Load this column of all 24 slot rows into registers (coalesced across d).
    float sv[S];
    const float* sb = slots + (size_t)b * S * D + d;
    #pragma unroll
    for (int j = 0; j < S; j++) sv[j] = sb[j * D];

    float* ob = out_slots + (size_t)b * S * D + d;
    #pragma unroll
    for (int i = 0; i < S; i++) {
        float acc = 0.0f;
        #pragma unroll
        for (int j = 0; j < S; j++)
            if (cl[j] == i) acc += sv[j];
        ob[i * D] = acc / ((float)cnt[i] + EPS);
    }

    if (d == 0) {
        int n = 0;
        #pragma unroll
        for (int i = 0; i < S; i++) n += (cnt[i] > 0);
        out_nums[b] = (float)n;
    }
}

// ---------------------------------------------------------------------------
// Kernel B: new_patch_attn [B,S,N], segment-sum + EPS + row-normalize
// grid = (S, B), 1024 threads; each thread owns 8 n-columns (2x float4)
// Each patch_attn row is read exactly once chip-wide (each j has one cluster)
// ---------------------------------------------------------------------------
__global__ void __launch_bounds__(1024) attn_kernel(
    const float* __restrict__ pa,        // [B,S,N]
    const int* __restrict__ clusters,    // [B,S]
    float* __restrict__ out)             // [B,S,N]
{
    const int i = blockIdx.x;   // cluster id 0..S-1
    const int b = blockIdx.y;
    const int t = threadIdx.x;  // 0..1023

    __shared__ int cl[S];
    __shared__ float wsum[32];

    if (t < S) cl[t] = clusters[b * S + t];
    __syncthreads();

    const float4* base = (const float4*)(pa + (size_t)b * S * N);
    float4 a0 = make_float4(EPS, EPS, EPS, EPS);
    float4 a1 = a0;

    #pragma unroll
    for (int j = 0; j < S; j++) {
        if (cl[j] == i) {  // uniform across block: no divergence
            const float4* row = base + (size_t)j * (N / 4);
            float4 v0 = row[t];
            float4 v1 = row[t + 1024];
            a0.x += v0.x; a0.y += v0.y; a0.z += v0.z; a0.w += v0.w;
            a1.x += v1.x; a1.y += v1.y; a1.z += v1.z; a1.w += v1.w;
        }
    }

    // Block reduction of the row sum (for normalization)
    float ls = (a0.x + a0.y) + (a0.z + a0.w) + (a1.x + a1.y) + (a1.z + a1.w);
    #pragma unroll
    for (int off = 16; off > 0; off >>= 1)
        ls += __shfl_xor_sync(0xFFFFFFFFu, ls, off);
    int warp = t >> 5, lane = t & 31;
    if (lane == 0) wsum[warp] = ls;
    __syncthreads();
    if (warp == 0) {
        float v = wsum[lane];  // 32 warps exactly
        #pragma unroll
        for (int off = 16; off > 0; off >>= 1)
            v += __shfl_xor_sync(0xFFFFFFFFu, v, off);
        if (lane == 0) wsum[0] = v;
    }
    __syncthreads();
    const float inv = 1.0f / wsum[0];

    float4* o = (float4*)(out + (size_t)(b * S + i) * N);
    float4 r0 = make_float4(a0.x * inv, a0.y * inv, a0.z * inv, a0.w * inv);
    float4 r1 = make_float4(a1.x * inv, a1.y * inv, a1.z * inv, a1.w * inv);
    o[t] = r0;
    o[t + 1024] = r1;
}

// ---------------------------------------------------------------------------
extern "C" void kernel_launch(void* const* d_in, const int* in_sizes, int n_in,
                              void* d_out, int out_size)
{
    const float* slots    = (const float*)d_in[0];   // [B,S,D]
    const float* pa       = (const float*)d_in[1];   // [B,S,N]
    const int*   clusters = (const int*)d_in[2];     // [B,S] int32

    float* out = (float*)d_out;
    float* out_slots = out;                              // [B,S,D]
    float* out_attn  = out + (size_t)B * S * D;          // [B,S,N]
    float* out_nums  = out_attn + (size_t)B * S * N;     // [B]

    slots_kernel<<<B, 256>>>(slots, clusters, out_slots, out_nums);
    attn_kernel<<<dim3(S, B), 1024>>>(pa, clusters, out_attn);
}